// round 6
// baseline (speedup 1.0000x reference)
#include <cuda_runtime.h>

#define LN_EPS 1e-5f
#define D_EPS  1e-6f
#define BATCH  16
#define SEQL   2048
#define NCHUNK 32           // 32 chunks x 64 steps = 2048 (2047 real + 1 pad)

// Scratch
__device__ float g_tab[64 * 64];
__device__ float g_G[64 * 64];                     // Gram
__device__ float g_TW[64 * 64];                    // Tab @ Wr
__device__ float g_rpos[64];                       // 1/(||tab||^2 + eps)
__device__ float g_Ainv[BATCH * NCHUNK * 64 * 64]; // per-chunk (I+L)^-1
__device__ float g_Gsub[BATCH * NCHUNK * 64 * 64]; // per-chunk gathered G cols

// ---------------------------------------------------------------------------
// K1: per-token table: tab[a] = LN(e_a + MLP(e_a)); rpos = 1/(||tab||^2+eps)
// ---------------------------------------------------------------------------
__global__ __launch_bounds__(128) void table_kernel(
    const float* __restrict__ embed, const float* __restrict__ W1,
    const float* __restrict__ b1, const float* __restrict__ W2,
    const float* __restrict__ b2, const float* __restrict__ gamma,
    const float* __restrict__ beta)
{
    __shared__ float hs[64];
    __shared__ float t1s[128];
    __shared__ float xh[2][64];
    __shared__ float red[2][2];

    const int a = blockIdx.x, tid = threadIdx.x;
    if (tid < 64) hs[tid] = embed[a * 64 + tid];
    __syncthreads();

    float acc = b1[tid];
    #pragma unroll
    for (int i = 0; i < 64; i++) acc = fmaf(hs[i], W1[i * 128 + tid], acc);
    t1s[tid] = fmaxf(acc, 0.f);
    __syncthreads();

    {
        int j = tid & 63, half = tid >> 6;
        float a2 = 0.f;
        #pragma unroll
        for (int ii = 0; ii < 64; ii++) {
            int i = half * 64 + ii;
            a2 = fmaf(t1s[i], W2[i * 64 + j], a2);
        }
        xh[half][j] = a2;
    }
    __syncthreads();

    float x = 0.f, y = 0.f;
    if (tid < 64) {
        x = hs[tid] + xh[0][tid] + xh[1][tid] + b2[tid];
        float s = x, q = x * x;
        #pragma unroll
        for (int o = 16; o > 0; o >>= 1) {
            s += __shfl_xor_sync(0xffffffffu, s, o);
            q += __shfl_xor_sync(0xffffffffu, q, o);
        }
        if ((tid & 31) == 0) { red[tid >> 5][0] = s; red[tid >> 5][1] = q; }
    }
    __syncthreads();
    if (tid < 64) {
        float S = red[0][0] + red[1][0];
        float Q = red[0][1] + red[1][1];
        float mu = S * (1.0f / 64.0f);
        float var = Q * (1.0f / 64.0f) - mu * mu;
        y = (x - mu) * rsqrtf(var + LN_EPS) * gamma[tid] + beta[tid];
        g_tab[a * 64 + tid] = y;
        float z = y * y;
        #pragma unroll
        for (int o = 16; o > 0; o >>= 1) z += __shfl_xor_sync(0xffffffffu, z, o);
        if ((tid & 31) == 0) red[tid >> 5][0] = z;
    }
    __syncthreads();
    if (tid == 0) {
        float d = red[0][0] + red[1][0] + D_EPS;
        g_rpos[a] = 1.0f / d;
    }
}

// ---------------------------------------------------------------------------
// K2: G = Tab Tab^T and TW = Tab @ Wr.
// ---------------------------------------------------------------------------
__global__ __launch_bounds__(64) void gram_kernel(const float* __restrict__ Wr)
{
    __shared__ float T[64][65];
    const int a = blockIdx.x, t = threadIdx.x;
    for (int r = 0; r < 64; r++) T[r][t] = g_tab[r * 64 + t];
    __syncthreads();
    float g = 0.f, tw = 0.f;
    #pragma unroll
    for (int h = 0; h < 64; h++) {
        float av = T[a][h];
        g  = fmaf(av, T[t][h], g);
        tw = fmaf(av, Wr[h * 64 + t], tw);
    }
    g_G[a * 64 + t]  = g;
    g_TW[a * 64 + t] = tw;
}

// ---------------------------------------------------------------------------
// K3: per-chunk prep. block = b*32 + c. 64 threads.
//   L[t][u] = r_u * G[v_t][v_u] (u<t);  Ainv = (I+L)^{-1} via column-owned
//   register forward substitution (no syncs in sweep); Gsub[a][j] = G[a][v_j].
// ---------------------------------------------------------------------------
__global__ __launch_bounds__(64) void prep_kernel(const int* __restrict__ seq)
{
    __shared__ int   vtok[64];
    __shared__ float rr[64];
    __shared__ float Lsh[64][65];

    const int blk = blockIdx.x;
    const int b = blk >> 5, c = blk & 31;
    const int t = threadIdx.x;
    const int* sq = seq + b * SEQL;

    {
        int i = c * 64 + t;                     // reversed global step index
        int v = (i < 2047) ? sq[2046 - i] : 0;  // step 2047 is pad
        vtok[t] = v;
        rr[t]   = (i < 2047) ? g_rpos[v] : 0.f;
    }
    __syncthreads();

    // Gsub row t
    {
        float* dst = g_Gsub + (size_t)blk * 4096 + t * 64;
        const float* gr = g_G + t * 64;
        #pragma unroll 8
        for (int jj = 0; jj < 64; jj++) dst[jj] = gr[vtok[jj]];
    }
    // L row t (strictly lower)
    {
        const float* gr = g_G + vtok[t] * 64;
        for (int u = 0; u < t; u++)
            Lsh[t][u] = rr[u] * gr[vtok[u]];
    }
    __syncthreads();

    // forward substitution: thread t owns column t of X = (I+L)^{-1}
    float X[64];
    #pragma unroll
    for (int i2 = 0; i2 < 64; i2++) X[i2] = (i2 == t) ? 1.f : 0.f;
    #pragma unroll
    for (int u = 0; u < 63; u++) {
        float xu = X[u];
        #pragma unroll
        for (int tt = u + 1; tt < 64; tt++)
            X[tt] = fmaf(-Lsh[tt][u], xu, X[tt]);
    }
    __syncthreads();

    // transpose via smem, then coalesced row store
    #pragma unroll
    for (int i2 = 0; i2 < 64; i2++) Lsh[i2][t] = X[i2];
    __syncthreads();
    {
        float4* dst = (float4*)(g_Ainv + (size_t)blk * 4096 + t * 64);
        const float* src = &Lsh[t][0];
        #pragma unroll
        for (int j4 = 0; j4 < 16; j4++)
            dst[j4] = make_float4(src[4*j4], src[4*j4+1], src[4*j4+2], src[4*j4+3]);
    }
}

// ---------------------------------------------------------------------------
// K4: chain (32 sequential chunk-GEMVs) + s/beta recovery + head. 1 blk/batch.
// 256 threads = 64 rows x 4 lanes. Ainv/Gsub prefetched one chunk ahead.
// ---------------------------------------------------------------------------
__global__ __launch_bounds__(256) void chain_kernel(
    const int* __restrict__ seq,
    const float* __restrict__ br, const float* __restrict__ Wo,
    const float* __restrict__ bo, float* __restrict__ out)
{
    __shared__ int   vsh[SEQL];
    __shared__ float rstep[SEQL];
    __shared__ float psh[NCHUNK][64];
    __shared__ float ssh[SEQL];
    __shared__ float wsh[64];
    __shared__ float tsh[64];
    __shared__ float betash[64];
    __shared__ float part[4][64];
    __shared__ float hed[64];

    const int b = blockIdx.x, tid = threadIdx.x;
    const int j = tid >> 2, q = tid & 3;
    const int* sq = seq + b * SEQL;

    for (int i = tid; i < SEQL; i += 256) {
        int v = (i < 2047) ? sq[2046 - i] : 0;
        vsh[i] = v;
        rstep[i] = (i < 2047) ? g_rpos[v] : 0.f;
    }
    if (tid < 64) wsh[tid] = g_G[tid * 64 + sq[SEQL - 1]];
    __syncthreads();

    const float* Ab = g_Ainv + (size_t)b * NCHUNK * 4096;
    const float* Gb = g_Gsub + (size_t)b * NCHUNK * 4096;
    const int lane_off = j * 64 + q * 16;

    float4 a0, a1, a2, a3, g0, g1, g2, g3;
    {
        const float4* ap = (const float4*)(Ab + lane_off);
        a0 = ap[0]; a1 = ap[1]; a2 = ap[2]; a3 = ap[3];
        const float4* gp = (const float4*)(Gb + lane_off);
        g0 = gp[0]; g1 = gp[1]; g2 = gp[2]; g3 = gp[3];
    }
    float wreg = (q == 0) ? wsh[j] : 0.f;

    for (int c = 0; c < NCHUNK; c++) {
        // prefetch next chunk operands (hide L2 latency behind this chunk)
        int cn = (c + 1 < NCHUNK) ? c + 1 : c;
        const float4* anp = (const float4*)(Ab + cn * 4096 + lane_off);
        const float4* gnp = (const float4*)(Gb + cn * 4096 + lane_off);
        float4 na0 = anp[0], na1 = anp[1], na2 = anp[2], na3 = anp[3];
        float4 ng0 = gnp[0], ng1 = gnp[1], ng2 = gnp[2], ng3 = gnp[3];

        // gather p = w[v_j]
        if (tid < 64) psh[c][tid] = wsh[vsh[c * 64 + tid]];
        __syncthreads();

        // s_j = (Ainv p)_j  (4 lanes per row, dot-16 + 2 shfls)
        {
            const float4* pc = (const float4*)(psh[c] + q * 16);
            float4 p0 = pc[0], p1 = pc[1], p2 = pc[2], p3 = pc[3];
            float u0 = fmaf(a0.x, p0.x, a0.y * p0.y);
            u0 = fmaf(a0.z, p0.z, u0); u0 = fmaf(a0.w, p0.w, u0);
            float u1 = fmaf(a1.x, p1.x, a1.y * p1.y);
            u1 = fmaf(a1.z, p1.z, u1); u1 = fmaf(a1.w, p1.w, u1);
            float u2 = fmaf(a2.x, p2.x, a2.y * p2.y);
            u2 = fmaf(a2.z, p2.z, u2); u2 = fmaf(a2.w, p2.w, u2);
            float u3 = fmaf(a3.x, p3.x, a3.y * p3.y);
            u3 = fmaf(a3.z, p3.z, u3); u3 = fmaf(a3.w, p3.w, u3);
            float sv = (u0 + u1) + (u2 + u3);
            sv += __shfl_xor_sync(0xffffffffu, sv, 1);
            sv += __shfl_xor_sync(0xffffffffu, sv, 2);
            if (q == 0) tsh[j] = sv * rstep[c * 64 + j];
        }
        __syncthreads();

        // w[j] -= sum_l Gsub[j][l] * t_l
        {
            const float4* tc = (const float4*)(tsh + q * 16);
            float4 t0 = tc[0], t1 = tc[1], t2 = tc[2], t3 = tc[3];
            float u0 = fmaf(g0.x, t0.x, g0.y * t0.y);
            u0 = fmaf(g0.z, t0.z, u0); u0 = fmaf(g0.w, t0.w, u0);
            float u1 = fmaf(g1.x, t1.x, g1.y * t1.y);
            u1 = fmaf(g1.z, t1.z, u1); u1 = fmaf(g1.w, t1.w, u1);
            float u2 = fmaf(g2.x, t2.x, g2.y * t2.y);
            u2 = fmaf(g2.z, t2.z, u2); u2 = fmaf(g2.w, t2.w, u2);
            float u3 = fmaf(g3.x, t3.x, g3.y * t3.y);
            u3 = fmaf(g3.z, t3.z, u3); u3 = fmaf(g3.w, t3.w, u3);
            float du = (u0 + u1) + (u2 + u3);
            du += __shfl_xor_sync(0xffffffffu, du, 1);
            du += __shfl_xor_sync(0xffffffffu, du, 2);
            if (q == 0) { wreg -= du; wsh[j] = wreg; }
        }
        a0 = na0; a1 = na1; a2 = na2; a3 = na3;
        g0 = ng0; g1 = ng1; g2 = ng2; g3 = ng3;
        __syncthreads();
    }

    // recover s for every step: s = Ainv_c p_c (deterministic, parallel)
    for (int idx = tid; idx < SEQL; idx += 256) {
        int cc = idx >> 6, jj = idx & 63;
        const float4* arow = (const float4*)(Ab + cc * 4096 + jj * 64);
        const float* pp = psh[cc];
        float acc = 0.f;
        #pragma unroll
        for (int l4 = 0; l4 < 16; l4++) {
            float4 av = arow[l4];
            acc = fmaf(av.x, pp[4*l4+0], acc);
            acc = fmaf(av.y, pp[4*l4+1], acc);
            acc = fmaf(av.z, pp[4*l4+2], acc);
            acc = fmaf(av.w, pp[4*l4+3], acc);
        }
        ssh[idx] = (idx < 2047) ? acc : 0.f;
    }
    __syncthreads();

    // beta[a] = sum_{i: v_i = a} s_i  (gather, deterministic)
    {
        int a = tid & 63, qd = tid >> 6;
        float p = 0.f;
        for (int i = qd * 4; i < SEQL; i += 16) {
            float4 sx = *(const float4*)&ssh[i];
            int4 vv = *(const int4*)&vsh[i];
            if (vv.x == a) p += sx.x;
            if (vv.y == a) p += sx.y;
            if (vv.z == a) p += sx.z;
            if (vv.w == a) p += sx.w;
        }
        part[qd][a] = p;
    }
    __syncthreads();
    if (tid < 64)
        betash[tid] = part[0][tid] + part[1][tid] + part[2][tid] + part[3][tid];
    __syncthreads();

    // head: out = (beta @ TW + br) @ Wo + bo
    if (tid < 64) {
        float acc = br[tid];
        #pragma unroll
        for (int a = 0; a < 64; a++)
            acc = fmaf(betash[a], g_TW[a * 64 + tid], acc);
        hed[tid] = acc;
    }
    __syncthreads();
    if (tid < 64) {
        float o = bo[tid];
        #pragma unroll
        for (int k = 0; k < 64; k++)
            o = fmaf(hed[k], Wo[k * 64 + tid], o);
        out[b * 64 + tid] = o;
    }
}

// ---------------------------------------------------------------------------
extern "C" void kernel_launch(void* const* d_in, const int* in_sizes, int n_in,
                              void* d_out, int out_size)
{
    const int*   seq   = (const int*)d_in[0];
    const float* embed = (const float*)d_in[1];
    const float* W1    = (const float*)d_in[2];
    const float* b1    = (const float*)d_in[3];
    const float* W2    = (const float*)d_in[4];
    const float* b2    = (const float*)d_in[5];
    const float* gamma = (const float*)d_in[6];
    const float* beta  = (const float*)d_in[7];
    const float* Wr    = (const float*)d_in[8];
    const float* br    = (const float*)d_in[9];
    const float* Wo    = (const float*)d_in[10];
    const float* bo    = (const float*)d_in[11];
    float* out = (float*)d_out;

    table_kernel<<<64, 128>>>(embed, W1, b1, W2, b2, gamma, beta);
    gram_kernel<<<64, 64>>>(Wr);
    prep_kernel<<<BATCH * NCHUNK, 64>>>(seq);
    chain_kernel<<<BATCH, 256>>>(seq, br, Wo, bo, out);
}

// round 7
// speedup vs baseline: 1.6075x; 1.6075x over previous
#include <cuda_runtime.h>
#include <cstdint>

#define LN_EPS 1e-5f
#define D_EPS  1e-6f
#define BATCH  16
#define SEQL   2048
#define NCHUNK 32           // 32 chunks x 64 steps = 2048 (2047 real + 1 pad)

// Scratch
__device__ float g_tab[64 * 64];
__device__ float g_G[64 * 64];                     // Gram
__device__ float g_TW[64 * 64];                    // Tab @ Wr
__device__ float g_rpos[64];                       // 1/(||tab||^2 + eps)
__device__ float g_dpos[64];                       // (||tab||^2 + eps)
__device__ float g_Ainv[BATCH * NCHUNK * 64 * 64]; // per-chunk (I+L)^-1

// ---------------------------------------------------------------------------
__device__ __forceinline__ void cp_async16(uint32_t saddr, const void* gaddr) {
    asm volatile("cp.async.cg.shared.global [%0], [%1], 16;"
                 :: "r"(saddr), "l"(gaddr));
}
__device__ __forceinline__ void cp_commit() {
    asm volatile("cp.async.commit_group;");
}
__device__ __forceinline__ void cp_wait1() {
    asm volatile("cp.async.wait_group 1;");
}

// ---------------------------------------------------------------------------
// K1: per-token table: tab[a] = LN(e_a + MLP(e_a)); rpos/dpos.
// ---------------------------------------------------------------------------
__global__ __launch_bounds__(128) void table_kernel(
    const float* __restrict__ embed, const float* __restrict__ W1,
    const float* __restrict__ b1, const float* __restrict__ W2,
    const float* __restrict__ b2, const float* __restrict__ gamma,
    const float* __restrict__ beta)
{
    __shared__ float hs[64];
    __shared__ float t1s[128];
    __shared__ float xh[2][64];
    __shared__ float red[2][2];

    const int a = blockIdx.x, tid = threadIdx.x;
    if (tid < 64) hs[tid] = embed[a * 64 + tid];
    __syncthreads();

    float acc = b1[tid];
    #pragma unroll
    for (int i = 0; i < 64; i++) acc = fmaf(hs[i], W1[i * 128 + tid], acc);
    t1s[tid] = fmaxf(acc, 0.f);
    __syncthreads();

    {
        int j = tid & 63, half = tid >> 6;
        float a2 = 0.f;
        #pragma unroll
        for (int ii = 0; ii < 64; ii++) {
            int i = half * 64 + ii;
            a2 = fmaf(t1s[i], W2[i * 64 + j], a2);
        }
        xh[half][j] = a2;
    }
    __syncthreads();

    float x = 0.f, y = 0.f;
    if (tid < 64) {
        x = hs[tid] + xh[0][tid] + xh[1][tid] + b2[tid];
        float s = x, q = x * x;
        #pragma unroll
        for (int o = 16; o > 0; o >>= 1) {
            s += __shfl_xor_sync(0xffffffffu, s, o);
            q += __shfl_xor_sync(0xffffffffu, q, o);
        }
        if ((tid & 31) == 0) { red[tid >> 5][0] = s; red[tid >> 5][1] = q; }
    }
    __syncthreads();
    if (tid < 64) {
        float S = red[0][0] + red[1][0];
        float Q = red[0][1] + red[1][1];
        float mu = S * (1.0f / 64.0f);
        float var = Q * (1.0f / 64.0f) - mu * mu;
        y = (x - mu) * rsqrtf(var + LN_EPS) * gamma[tid] + beta[tid];
        g_tab[a * 64 + tid] = y;
        float z = y * y;
        #pragma unroll
        for (int o = 16; o > 0; o >>= 1) z += __shfl_xor_sync(0xffffffffu, z, o);
        if ((tid & 31) == 0) red[tid >> 5][0] = z;
    }
    __syncthreads();
    if (tid == 0) {
        float d = red[0][0] + red[1][0] + D_EPS;
        g_dpos[a] = d;
        g_rpos[a] = 1.0f / d;
    }
}

// ---------------------------------------------------------------------------
// K2: G = Tab Tab^T and TW = Tab @ Wr.
// ---------------------------------------------------------------------------
__global__ __launch_bounds__(64) void gram_kernel(const float* __restrict__ Wr)
{
    __shared__ float T[64][65];
    const int a = blockIdx.x, t = threadIdx.x;
    for (int r = 0; r < 64; r++) T[r][t] = g_tab[r * 64 + t];
    __syncthreads();
    float g = 0.f, tw = 0.f;
    #pragma unroll
    for (int h = 0; h < 64; h++) {
        float av = T[a][h];
        g  = fmaf(av, T[t][h], g);
        tw = fmaf(av, Wr[h * 64 + t], tw);
    }
    g_G[a * 64 + t]  = g;
    g_TW[a * 64 + t] = tw;
}

// ---------------------------------------------------------------------------
// K3: per-chunk prep: Ainv = (I+L)^{-1}, L[t][u] = r_u * G[v_t][v_u] (u<t).
// block = b*32 + c; 64 threads; column-owned forward substitution.
// ---------------------------------------------------------------------------
__global__ __launch_bounds__(64) void prep_kernel(const int* __restrict__ seq)
{
    __shared__ int   vtok[64];
    __shared__ float rr[64];
    __shared__ float Lsh[64][65];

    const int blk = blockIdx.x;
    const int b = blk >> 5, c = blk & 31;
    const int t = threadIdx.x;
    const int* sq = seq + b * SEQL;

    {
        int i = c * 64 + t;                     // reversed global step index
        int v = (i < 2047) ? sq[2046 - i] : 0;  // step 2047 is pad
        vtok[t] = v;
        rr[t]   = (i < 2047) ? g_rpos[v] : 0.f;
    }
    __syncthreads();

    // L row t (strictly lower)
    {
        const float* gr = g_G + vtok[t] * 64;
        for (int u = 0; u < t; u++)
            Lsh[t][u] = rr[u] * gr[vtok[u]];
    }
    __syncthreads();

    // forward substitution: thread t owns column t of X = (I+L)^{-1}
    float X[64];
    #pragma unroll
    for (int i2 = 0; i2 < 64; i2++) X[i2] = (i2 == t) ? 1.f : 0.f;
    #pragma unroll
    for (int u = 0; u < 63; u++) {
        float xu = X[u];
        #pragma unroll
        for (int tt = u + 1; tt < 64; tt++)
            X[tt] = fmaf(-Lsh[tt][u], xu, X[tt]);
    }
    __syncthreads();

    // transpose via smem, then coalesced row store (row-major Ainv[j][l])
    #pragma unroll
    for (int i2 = 0; i2 < 64; i2++) Lsh[i2][t] = X[i2];
    __syncthreads();
    {
        float4* dst = (float4*)(g_Ainv + (size_t)blk * 4096 + t * 64);
        const float* src = &Lsh[t][0];
        #pragma unroll
        for (int j4 = 0; j4 < 16; j4++)
            dst[j4] = make_float4(src[4*j4], src[4*j4+1], src[4*j4+2], src[4*j4+3]);
    }
}

// ---------------------------------------------------------------------------
// K4: chain. 1 block/batch, 256 threads = 64 rows x 4 lanes.
// Ainv streamed by cp.async (distance 2, 3 smem buffers, stride-68 rows).
// Per chunk: p gather from wsh; s = Ainv p; t = r.s -> tall; w -= Gp[:,v].t
// Post: beta[a] = d_a * sum_{v_i=a} t_i; head -> out.
// ---------------------------------------------------------------------------
// smem float offsets
#define OFF_GP   0          // 64*65   = 4160
#define OFF_AB   4160       // 3*4352  = 13056
#define OFF_TALL 17216      // 32*68   = 2176
#define OFF_RST  19392      // 2048    (reused as betash after loop)
#define OFF_W    21440      // 64
#define OFF_VB   21504      // 512 floats = 2048 uchar
#define OFF_PART 22016      // 256
#define OFF_HED  22272      // 64
#define SMEM_FLOATS 22336
#define SMEM_BYTES  (SMEM_FLOATS * 4)
#define ASTRIDE 68

__global__ __launch_bounds__(256) void chain_kernel(
    const int* __restrict__ seq,
    const float* __restrict__ br, const float* __restrict__ Wo,
    const float* __restrict__ bo, float* __restrict__ out)
{
    extern __shared__ float sm[];
    float* Gp   = sm + OFF_GP;
    float* Ab   = sm + OFF_AB;
    float* tall = sm + OFF_TALL;
    float* rstep = sm + OFF_RST;
    float* wsh  = sm + OFF_W;
    unsigned char* vb = (unsigned char*)(sm + OFF_VB);
    float* part = sm + OFF_PART;
    float* hed  = sm + OFF_HED;

    const int b = blockIdx.x, tid = threadIdx.x;
    const int j = tid >> 2, q = tid & 3;
    const int* sq = seq + b * SEQL;
    const float* Agl = g_Ainv + (size_t)b * NCHUNK * 4096;

    // cp.async issue helper: 1024 16B segments per chunk, 4 per thread
    auto issue_chunk = [&](int c) {
        float* buf = Ab + (c % 3) * (64 * ASTRIDE);
        const float* src = Agl + c * 4096;
        #pragma unroll
        for (int k = 0; k < 4; k++) {
            int s = tid + k * 256;
            int row = s >> 4, w16 = s & 15;
            uint32_t sa = (uint32_t)__cvta_generic_to_shared(
                              buf + row * ASTRIDE + w16 * 4);
            cp_async16(sa, src + row * 64 + w16 * 4);
        }
    };

    issue_chunk(0); cp_commit();
    issue_chunk(1); cp_commit();

    // stage Gram (padded 65) and token stream
    for (int idx = tid; idx < 4096; idx += 256)
        Gp[(idx >> 6) * 65 + (idx & 63)] = g_G[idx];
    for (int i = tid; i < SEQL; i += 256) {
        int v = (i < 2047) ? sq[2046 - i] : 0;
        vb[i] = (unsigned char)v;
        rstep[i] = (i < 2047) ? g_rpos[v] : 0.f;
    }
    if (tid < 64) wsh[tid] = g_G[tid * 64 + sq[SEQL - 1]];

    for (int c = 0; c < NCHUNK; c++) {
        cp_wait1();
        __syncthreads();          // chunk c staged; prev phase2 done
        if (c + 2 < NCHUNK) issue_chunk(c + 2);
        cp_commit();

        const float* ab = Ab + (c % 3) * (64 * ASTRIDE) + j * ASTRIDE + q * 16;
        uint4 vv = *(const uint4*)(vb + c * 64 + q * 16);
        const unsigned v0  = vv.x & 255u,        v1  = (vv.x >> 8) & 255u,
                       v2  = (vv.x >> 16) & 255u, v3  = vv.x >> 24;
        const unsigned v4  = vv.y & 255u,        v5  = (vv.y >> 8) & 255u,
                       v6  = (vv.y >> 16) & 255u, v7  = vv.y >> 24;
        const unsigned v8  = vv.z & 255u,        v9  = (vv.z >> 8) & 255u,
                       v10 = (vv.z >> 16) & 255u, v11 = vv.z >> 24;
        const unsigned v12 = vv.w & 255u,        v13 = (vv.w >> 8) & 255u,
                       v14 = (vv.w >> 16) & 255u, v15 = vv.w >> 24;

        // phase 1: s_j = (Ainv p)_j, p_l = wsh[v_l]; t_j = s_j * r_j
        {
            float4 a0 = *(const float4*)(ab + 0);
            float4 a1 = *(const float4*)(ab + 4);
            float4 a2 = *(const float4*)(ab + 8);
            float4 a3 = *(const float4*)(ab + 12);
            float u0 = fmaf(a0.x, wsh[v0], a0.y * wsh[v1]);
            u0 = fmaf(a0.z, wsh[v2], u0); u0 = fmaf(a0.w, wsh[v3], u0);
            float u1 = fmaf(a1.x, wsh[v4], a1.y * wsh[v5]);
            u1 = fmaf(a1.z, wsh[v6], u1); u1 = fmaf(a1.w, wsh[v7], u1);
            float u2 = fmaf(a2.x, wsh[v8], a2.y * wsh[v9]);
            u2 = fmaf(a2.z, wsh[v10], u2); u2 = fmaf(a2.w, wsh[v11], u2);
            float u3 = fmaf(a3.x, wsh[v12], a3.y * wsh[v13]);
            u3 = fmaf(a3.z, wsh[v14], u3); u3 = fmaf(a3.w, wsh[v15], u3);
            float sv = (u0 + u1) + (u2 + u3);
            sv += __shfl_xor_sync(0xffffffffu, sv, 1);
            sv += __shfl_xor_sync(0xffffffffu, sv, 2);
            if (q == 0) tall[c * ASTRIDE + j] = sv * rstep[c * 64 + j];
        }
        __syncthreads();

        // phase 2: w[j] -= sum_l Gp[j][v_l] * t_l
        {
            const float* tr = tall + c * ASTRIDE + q * 16;
            float4 t0 = *(const float4*)(tr + 0);
            float4 t1 = *(const float4*)(tr + 4);
            float4 t2 = *(const float4*)(tr + 8);
            float4 t3 = *(const float4*)(tr + 12);
            const float* gr = Gp + j * 65;
            float u0 = fmaf(gr[v0], t0.x, gr[v1] * t0.y);
            u0 = fmaf(gr[v2], t0.z, u0); u0 = fmaf(gr[v3], t0.w, u0);
            float u1 = fmaf(gr[v4], t1.x, gr[v5] * t1.y);
            u1 = fmaf(gr[v6], t1.z, u1); u1 = fmaf(gr[v7], t1.w, u1);
            float u2 = fmaf(gr[v8], t2.x, gr[v9] * t2.y);
            u2 = fmaf(gr[v10], t2.z, u2); u2 = fmaf(gr[v11], t2.w, u2);
            float u3 = fmaf(gr[v12], t3.x, gr[v13] * t3.y);
            u3 = fmaf(gr[v14], t3.z, u3); u3 = fmaf(gr[v15], t3.w, u3);
            float du = (u0 + u1) + (u2 + u3);
            du += __shfl_xor_sync(0xffffffffu, du, 1);
            du += __shfl_xor_sync(0xffffffffu, du, 2);
            if (q == 0) wsh[j] -= du;
        }
    }
    __syncthreads();

    // beta partials: part[qd][a] = sum over chunks qd,qd+4,... of t where v==a
    {
        const int a = tid & 63, qd = tid >> 6;
        float p = 0.f;
        for (int c = qd; c < NCHUNK; c += 4) {
            const float* tr = tall + c * ASTRIDE;
            const unsigned char* vr = vb + c * 64;
            #pragma unroll 4
            for (int j0 = 0; j0 < 64; j0 += 4) {
                uchar4 vq4 = *(const uchar4*)(vr + j0);
                float4 tv = *(const float4*)(tr + j0);
                if (vq4.x == a) p += tv.x;
                if (vq4.y == a) p += tv.y;
                if (vq4.z == a) p += tv.z;
                if (vq4.w == a) p += tv.w;
            }
        }
        part[qd * 64 + a] = p;
    }
    __syncthreads();
    float* betash = rstep;   // reuse
    if (tid < 64)
        betash[tid] = (part[tid] + part[64 + tid] + part[128 + tid]
                       + part[192 + tid]) * g_dpos[tid];
    __syncthreads();

    // head: out = (beta @ TW + br) @ Wo + bo
    if (tid < 64) {
        float acc = br[tid];
        #pragma unroll
        for (int a = 0; a < 64; a++)
            acc = fmaf(betash[a], g_TW[a * 64 + tid], acc);
        hed[tid] = acc;
    }
    __syncthreads();
    if (tid < 64) {
        float o = bo[tid];
        #pragma unroll
        for (int k = 0; k < 64; k++)
            o = fmaf(hed[k], Wo[k * 64 + tid], o);
        out[b * 64 + tid] = o;
    }
}

// ---------------------------------------------------------------------------
extern "C" void kernel_launch(void* const* d_in, const int* in_sizes, int n_in,
                              void* d_out, int out_size)
{
    const int*   seq   = (const int*)d_in[0];
    const float* embed = (const float*)d_in[1];
    const float* W1    = (const float*)d_in[2];
    const float* b1    = (const float*)d_in[3];
    const float* W2    = (const float*)d_in[4];
    const float* b2    = (const float*)d_in[5];
    const float* gamma = (const float*)d_in[6];
    const float* beta  = (const float*)d_in[7];
    const float* Wr    = (const float*)d_in[8];
    const float* br    = (const float*)d_in[9];
    const float* Wo    = (const float*)d_in[10];
    const float* bo    = (const float*)d_in[11];
    float* out = (float*)d_out;

    cudaFuncSetAttribute(chain_kernel,
                         cudaFuncAttributeMaxDynamicSharedMemorySize,
                         SMEM_BYTES);

    table_kernel<<<64, 128>>>(embed, W1, b1, W2, b2, gamma, beta);
    gram_kernel<<<64, 64>>>(Wr);
    prep_kernel<<<BATCH * NCHUNK, 64>>>(seq);
    chain_kernel<<<BATCH, 256, SMEM_BYTES>>>(seq, br, Wo, bo, out);
}